// round 9
// baseline (speedup 1.0000x reference)
#include <cuda_runtime.h>

// Problem constants (from reference): N=1048576 rows, H=128, B=1024 segments.
#define H_DIM 128
#define EPS 1e-12f
#define MAX_B 4096          // scratch sized generously vs B=1024
#define MAX_N (1 << 20)     // N = 1048576

// Precomputed w[s,h] = d[h] * summary[s,h]  (512KB for B=1024)
__device__ float g_wbuf[MAX_B * H_DIM];
// Precomputed row -> segment id (2MB for N=1M)
__device__ unsigned short g_seg[MAX_N];

// Fused prep: blocks [0, n_seg) fill the seg table (one block per segment),
// blocks [n_seg, n_seg + w_blocks) compute w = d (*) summary.
__global__ void __launch_bounds__(256) prep_kernel(
    const float* __restrict__ summary,
    const float* __restrict__ dvec,
    const int*   __restrict__ ptr,
    int n_rows, int n_seg, int w_total)
{
    const int b = blockIdx.x;
    if (b < n_seg) {
        const int start = ptr[b];
        const int end   = min(ptr[b + 1], n_rows);
        for (int i = start + (int)threadIdx.x; i < end; i += 256)
            g_seg[i] = (unsigned short)b;
    } else {
        const int i = (b - n_seg) * 256 + (int)threadIdx.x;
        if (i < w_total)
            g_wbuf[i] = summary[i] * dvec[i & (H_DIM - 1)];
    }
}

// 4 rows per warp; each 8-lane group owns one row.
// Lane g holds float4 columns {g, g+8, g+16, g+24} of its row, so each
// warp-level load moves 4 rows x 128B = four FULL 128B lines.
// All 4 e-loads front-batched (16 live regs); total ~32 regs so 8 blocks/SM
// (64 warps, 100% theoretical occupancy) hide the DRAM latency.
__global__ void __launch_bounds__(256, 8) sim_kernel(
    const float* __restrict__ emb,
    const float* __restrict__ scale,
    float* __restrict__ out,
    int n_rows)
{
    const int wid  = (blockIdx.x * blockDim.x + threadIdx.x) >> 5;
    const int lane = threadIdx.x & 31;
    const int g    = lane & 7;        // position within 8-lane row group
    const int rsub = lane >> 3;       // which of the warp's 4 rows

    int row = wid * 4 + rsub;
    const bool valid = row < n_rows;
    row = min(row, n_rows - 1);

    // ---- independent cached loads issued first ----
    const int   seg = (int)g_seg[row];
    const float sc  = __ldg(scale);

    const float4* e4 = reinterpret_cast<const float4*>(emb)   + (size_t)row * (H_DIM / 4);
    const float4* w4 = reinterpret_cast<const float4*>(g_wbuf) + (size_t)seg * (H_DIM / 4);

    // ---- all 4 streaming loads front-batched ----
    const float4 e0 = __ldcs(&e4[g]);
    const float4 e1 = __ldcs(&e4[8 + g]);
    const float4 e2 = __ldcs(&e4[16 + g]);
    const float4 e3 = __ldcs(&e4[24 + g]);

    // Self-dot (norm) — consumes e as it lands.
    float ds;
    ds = e0.x * e0.x;
    ds = fmaf(e0.y, e0.y, ds); ds = fmaf(e0.z, e0.z, ds); ds = fmaf(e0.w, e0.w, ds);
    ds = fmaf(e1.x, e1.x, ds); ds = fmaf(e1.y, e1.y, ds);
    ds = fmaf(e1.z, e1.z, ds); ds = fmaf(e1.w, e1.w, ds);
    ds = fmaf(e2.x, e2.x, ds); ds = fmaf(e2.y, e2.y, ds);
    ds = fmaf(e2.z, e2.z, ds); ds = fmaf(e2.w, e2.w, ds);
    ds = fmaf(e3.x, e3.x, ds); ds = fmaf(e3.y, e3.y, ds);
    ds = fmaf(e3.z, e3.z, ds); ds = fmaf(e3.w, e3.w, ds);

    // Weighted dot — w loads are L1/L2 hits, consumed immediately
    // (keeps only one float4 of w live at a time).
    float dw;
    {
        const float4 w = __ldg(&w4[g]);
        dw = e0.x * w.x;
        dw = fmaf(e0.y, w.y, dw); dw = fmaf(e0.z, w.z, dw); dw = fmaf(e0.w, w.w, dw);
    }
    {
        const float4 w = __ldg(&w4[8 + g]);
        dw = fmaf(e1.x, w.x, dw); dw = fmaf(e1.y, w.y, dw);
        dw = fmaf(e1.z, w.z, dw); dw = fmaf(e1.w, w.w, dw);
    }
    {
        const float4 w = __ldg(&w4[16 + g]);
        dw = fmaf(e2.x, w.x, dw); dw = fmaf(e2.y, w.y, dw);
        dw = fmaf(e2.z, w.z, dw); dw = fmaf(e2.w, w.w, dw);
    }
    {
        const float4 w = __ldg(&w4[24 + g]);
        dw = fmaf(e3.x, w.x, dw); dw = fmaf(e3.y, w.y, dw);
        dw = fmaf(e3.z, w.z, dw); dw = fmaf(e3.w, w.w, dw);
    }

    // Reduce within each 8-lane group (3 butterfly steps, both sums).
    #pragma unroll
    for (int off = 4; off > 0; off >>= 1) {
        ds += __shfl_xor_sync(0xFFFFFFFFu, ds, off);
        dw += __shfl_xor_sync(0xFFFFFFFFu, dw, off);
    }

    if (g == 0 && valid) {
        __stcs(&out[row], sc * __fdividef(dw, fmaxf(sqrtf(ds), EPS)));
    }
}

extern "C" void kernel_launch(void* const* d_in, const int* in_sizes, int n_in,
                              void* d_out, int out_size)
{
    const float* emb     = (const float*)d_in[0];   // [N, H]
    const float* summary = (const float*)d_in[1];   // [B, H]
    const int*   ptr     = (const int*)d_in[2];     // [B+1] int32
    const float* dvec    = (const float*)d_in[3];   // [H]
    const float* scale   = (const float*)d_in[4];   // [1]
    float*       out     = (float*)d_out;           // [N]

    const int n_rows  = in_sizes[0] / H_DIM;   // N
    const int n_seg   = in_sizes[2] - 1;       // B
    const int w_total = in_sizes[1];           // B*H

    const int w_blocks = (w_total + 255) / 256;
    prep_kernel<<<n_seg + w_blocks, 256>>>(summary, dvec, ptr, n_rows, n_seg, w_total);

    // 4 rows per warp, 8 warps per block -> 32 rows per block.
    const int n_warps = (n_rows + 3) / 4;
    const int blocks  = (n_warps + 7) / 8;
    sim_kernel<<<blocks, 256>>>(emb, scale, out, n_rows);
}